// round 2
// baseline (speedup 1.0000x reference)
#include <cuda_runtime.h>

// Problem dims (fixed by the dataset)
#define NMAX 100000
#define EMAX 1600000
#define INC  128
#define HID  128
#define OUTC 64
#define EPS  1e-5f

// ---------------- scratch (no allocations allowed) ----------------
__device__ int   g_cnt[NMAX];
__device__ int   g_rowptr[NMAX + 1];
__device__ int   g_fill[NMAX];
__device__ int   g_col[EMAX];
__device__ float g_dinv[NMAX];
__device__ float g_h1[(size_t)NMAX * HID];   // (x@W1) * dinv[row]
__device__ float g_a1[(size_t)NMAX * HID];   // aggregated layer-1 output (pre-BN)
__device__ float g_h2[(size_t)NMAX * OUTC];  // (relu(bn(a1))@W2) * dinv[row]
__device__ float g_stats1[4 * HID];          // sum[128] sq[128] s[128] t[128]
__device__ float g_stats2[4 * OUTC];         // sum[64]  sq[64]  s[64]  t[64]

// ---------------- init ----------------
__global__ void zero_kernel(int n) {
    int i = blockIdx.x * blockDim.x + threadIdx.x;
    if (i < n)        g_cnt[i] = 0;
    if (i < 4 * HID)  g_stats1[i] = 0.f;
    if (i < 4 * OUTC) g_stats2[i] = 0.f;
}

// ---------------- degree count ----------------
__global__ void count_kernel(const int* __restrict__ dst, int E) {
    int i = blockIdx.x * blockDim.x + threadIdx.x;
    if (i < E) atomicAdd(&g_cnt[dst[i]], 1);
}

// ---------------- single-block prefix scan over 100k counts ----------------
__global__ void scan_kernel(int n) {
    __shared__ int wsum[32];
    __shared__ int s_carry;
    int tid = threadIdx.x, lane = tid & 31, wid = tid >> 5;
    if (tid == 0) { s_carry = 0; g_rowptr[0] = 0; }
    __syncthreads();
    for (int base = 0; base < n; base += 1024) {
        int i = base + tid;
        int v = (i < n) ? g_cnt[i] : 0;
        // warp inclusive scan
        int x = v;
        #pragma unroll
        for (int off = 1; off < 32; off <<= 1) {
            int y = __shfl_up_sync(0xffffffffu, x, off);
            if (lane >= off) x += y;
        }
        if (lane == 31) wsum[wid] = x;
        __syncthreads();
        if (wid == 0) {
            int w = wsum[lane];
            #pragma unroll
            for (int off = 1; off < 32; off <<= 1) {
                int y = __shfl_up_sync(0xffffffffu, w, off);
                if (lane >= off) w += y;
            }
            wsum[lane] = w;
        }
        __syncthreads();
        int incl = x + (wid > 0 ? wsum[wid - 1] : 0);
        int c = s_carry;
        if (i < n) {
            g_rowptr[i + 1] = c + incl;
            g_fill[i]       = c + incl - v;           // exclusive prefix
            g_dinv[i]       = rsqrtf((float)(v + 1)); // +1 self-loop
        }
        __syncthreads();
        if (tid == 1023) s_carry = c + wsum[31];
        __syncthreads();
    }
}

// ---------------- CSR fill ----------------
__global__ void fill_kernel(const int* __restrict__ src, const int* __restrict__ dst, int E) {
    int i = blockIdx.x * blockDim.x + threadIdx.x;
    if (i < E) {
        int d = dst[i];
        int pos = atomicAdd(&g_fill[d], 1);
        g_col[pos] = src[i];
    }
}

// ---------------- register-blocked SGEMM, K=128, full-N blocks ----------------
// C[row, :] = (op(A)[row, :] @ B) * dinv[row]
// PRE_BN: A elements pass through relu(a * s[k] + t[k]) (BN1+ReLU folded into load).
template <int BM, int BN, int TM, int TN, bool PRE_BN>
__global__ __launch_bounds__(256)
void gemm_kernel(const float* __restrict__ Aext, const float* __restrict__ B, int M) {
    __shared__ float As[16][BM];
    __shared__ float Bs[16][BN];
    __shared__ float sS[HID], sT[HID];

    const float* A = PRE_BN ? g_a1 : Aext;
    float*       C = PRE_BN ? g_h2 : g_h1;

    int tid = threadIdx.x;
    if (PRE_BN) {
        if (tid < HID) { sS[tid] = g_stats1[2 * HID + tid]; sT[tid] = g_stats1[3 * HID + tid]; }
        __syncthreads();
    }
    int m0 = blockIdx.x * BM;
    int tx = tid & 15, ty = tid >> 4;
    float acc[TM][TN];
    #pragma unroll
    for (int i = 0; i < TM; i++)
        #pragma unroll
        for (int j = 0; j < TN; j++) acc[i][j] = 0.f;

    for (int k0 = 0; k0 < 128; k0 += 16) {
        // load A tile (BM x 16), transpose into As[k][m]
        #pragma unroll
        for (int p = 0; p < BM / 64; p++) {
            int idx = tid + p * 256;
            int ar = idx >> 2;
            int ac = (idx & 3) * 4;
            int row = m0 + ar;
            float4 v = make_float4(0.f, 0.f, 0.f, 0.f);
            if (row < M) v = *(const float4*)&A[(size_t)row * 128 + k0 + ac];
            if (PRE_BN) {
                int k = k0 + ac;
                v.x = fmaxf(fmaf(v.x, sS[k + 0], sT[k + 0]), 0.f);
                v.y = fmaxf(fmaf(v.y, sS[k + 1], sT[k + 1]), 0.f);
                v.z = fmaxf(fmaf(v.z, sS[k + 2], sT[k + 2]), 0.f);
                v.w = fmaxf(fmaf(v.w, sS[k + 3], sT[k + 3]), 0.f);
            }
            As[ac + 0][ar] = v.x; As[ac + 1][ar] = v.y;
            As[ac + 2][ar] = v.z; As[ac + 3][ar] = v.w;
        }
        // load B tile (16 x BN)
        #pragma unroll
        for (int p = 0; p < BN / 64; p++) {
            int idx = tid + p * 256;
            int br = idx / (BN / 4);
            int bc = (idx % (BN / 4)) * 4;
            *(float4*)&Bs[br][bc] = *(const float4*)&B[(size_t)(k0 + br) * BN + bc];
        }
        __syncthreads();
        #pragma unroll
        for (int kk = 0; kk < 16; kk++) {
            float a[TM], b[TN];
            #pragma unroll
            for (int i = 0; i < TM / 4; i++)
                *(float4*)&a[i * 4] = *(const float4*)&As[kk][ty * TM + i * 4];
            #pragma unroll
            for (int j = 0; j < TN / 4; j++)
                *(float4*)&b[j * 4] = *(const float4*)&Bs[kk][tx * TN + j * 4];
            #pragma unroll
            for (int i = 0; i < TM; i++)
                #pragma unroll
                for (int j = 0; j < TN; j++) acc[i][j] = fmaf(a[i], b[j], acc[i][j]);
        }
        __syncthreads();
    }
    // epilogue: scale by dinv[row]
    #pragma unroll
    for (int i = 0; i < TM; i++) {
        int row = m0 + ty * TM + i;
        if (row < M) {
            float d = g_dinv[row];
            #pragma unroll
            for (int j = 0; j < TN / 4; j++) {
                float4 o;
                o.x = acc[i][j * 4 + 0] * d;
                o.y = acc[i][j * 4 + 1] * d;
                o.z = acc[i][j * 4 + 2] * d;
                o.w = acc[i][j * 4 + 3] * d;
                *(float4*)&C[(size_t)row * BN + tx * TN + j * 4] = o;
            }
        }
    }
}

// ---------------- aggregation, 128 cols: warp per node, float4 per lane ----------------
__global__ __launch_bounds__(256)
void agg128_kernel(const float* __restrict__ b, int n) {
    int gwarp  = (blockIdx.x * blockDim.x + threadIdx.x) >> 5;
    int lane   = threadIdx.x & 31;
    int nwarps = (gridDim.x * blockDim.x) >> 5;
    const float4* base = (const float4*)g_h1;
    float4 bb = ((const float4*)b)[lane];
    float4 sum = make_float4(0, 0, 0, 0), sq = make_float4(0, 0, 0, 0);

    for (int node = gwarp; node < n; node += nwarps) {
        int e0 = g_rowptr[node], e1 = g_rowptr[node + 1];
        float4 acc = base[(size_t)node * 32 + lane];  // self-loop term
        int e = e0;
        for (; e + 4 <= e1; e += 4) {
            int i0 = g_col[e], i1 = g_col[e + 1], i2 = g_col[e + 2], i3 = g_col[e + 3];
            float4 v0 = base[(size_t)i0 * 32 + lane];
            float4 v1 = base[(size_t)i1 * 32 + lane];
            float4 v2 = base[(size_t)i2 * 32 + lane];
            float4 v3 = base[(size_t)i3 * 32 + lane];
            acc.x += (v0.x + v1.x) + (v2.x + v3.x);
            acc.y += (v0.y + v1.y) + (v2.y + v3.y);
            acc.z += (v0.z + v1.z) + (v2.z + v3.z);
            acc.w += (v0.w + v1.w) + (v2.w + v3.w);
        }
        for (; e < e1; e++) {
            float4 v = base[(size_t)g_col[e] * 32 + lane];
            acc.x += v.x; acc.y += v.y; acc.z += v.z; acc.w += v.w;
        }
        float d = g_dinv[node];
        float4 o;
        o.x = fmaf(acc.x, d, bb.x); o.y = fmaf(acc.y, d, bb.y);
        o.z = fmaf(acc.z, d, bb.z); o.w = fmaf(acc.w, d, bb.w);
        ((float4*)g_a1)[(size_t)node * 32 + lane] = o;
        sum.x += o.x; sum.y += o.y; sum.z += o.z; sum.w += o.w;
        sq.x += o.x * o.x; sq.y += o.y * o.y; sq.z += o.z * o.z; sq.w += o.w * o.w;
    }
    // block-level stats reduce, then one global atomic per column per block
    __shared__ float ssum[HID], ssq[HID];
    int t = threadIdx.x;
    if (t < HID) { ssum[t] = 0.f; ssq[t] = 0.f; }
    __syncthreads();
    int c0 = lane * 4;
    atomicAdd(&ssum[c0 + 0], sum.x); atomicAdd(&ssum[c0 + 1], sum.y);
    atomicAdd(&ssum[c0 + 2], sum.z); atomicAdd(&ssum[c0 + 3], sum.w);
    atomicAdd(&ssq[c0 + 0], sq.x);  atomicAdd(&ssq[c0 + 1], sq.y);
    atomicAdd(&ssq[c0 + 2], sq.z);  atomicAdd(&ssq[c0 + 3], sq.w);
    __syncthreads();
    if (t < HID) {
        atomicAdd(&g_stats1[t], ssum[t]);
        atomicAdd(&g_stats1[HID + t], ssq[t]);
    }
}

// ---------------- aggregation, 64 cols: warp per node, float2 per lane ----------------
__global__ __launch_bounds__(256)
void agg64_kernel(const float* __restrict__ b, float* __restrict__ out, int n) {
    int gwarp  = (blockIdx.x * blockDim.x + threadIdx.x) >> 5;
    int lane   = threadIdx.x & 31;
    int nwarps = (gridDim.x * blockDim.x) >> 5;
    const float2* base = (const float2*)g_h2;
    float2 bb = ((const float2*)b)[lane];
    float2 sum = make_float2(0, 0), sq = make_float2(0, 0);

    for (int node = gwarp; node < n; node += nwarps) {
        int e0 = g_rowptr[node], e1 = g_rowptr[node + 1];
        float2 acc = base[(size_t)node * 32 + lane];
        int e = e0;
        for (; e + 4 <= e1; e += 4) {
            int i0 = g_col[e], i1 = g_col[e + 1], i2 = g_col[e + 2], i3 = g_col[e + 3];
            float2 v0 = base[(size_t)i0 * 32 + lane];
            float2 v1 = base[(size_t)i1 * 32 + lane];
            float2 v2 = base[(size_t)i2 * 32 + lane];
            float2 v3 = base[(size_t)i3 * 32 + lane];
            acc.x += (v0.x + v1.x) + (v2.x + v3.x);
            acc.y += (v0.y + v1.y) + (v2.y + v3.y);
        }
        for (; e < e1; e++) {
            float2 v = base[(size_t)g_col[e] * 32 + lane];
            acc.x += v.x; acc.y += v.y;
        }
        float d = g_dinv[node];
        float2 o;
        o.x = fmaf(acc.x, d, bb.x); o.y = fmaf(acc.y, d, bb.y);
        ((float2*)out)[(size_t)node * 32 + lane] = o;
        sum.x += o.x; sum.y += o.y;
        sq.x += o.x * o.x; sq.y += o.y * o.y;
    }
    __shared__ float ssum[OUTC], ssq[OUTC];
    int t = threadIdx.x;
    if (t < OUTC) { ssum[t] = 0.f; ssq[t] = 0.f; }
    __syncthreads();
    int c0 = lane * 2;
    atomicAdd(&ssum[c0 + 0], sum.x); atomicAdd(&ssum[c0 + 1], sum.y);
    atomicAdd(&ssq[c0 + 0], sq.x);  atomicAdd(&ssq[c0 + 1], sq.y);
    __syncthreads();
    if (t < OUTC) {
        atomicAdd(&g_stats2[t], ssum[t]);
        atomicAdd(&g_stats2[OUTC + t], ssq[t]);
    }
}

// ---------------- BN params: s = gamma*rsqrt(var+eps), t = beta - mean*s ----------------
__global__ void bnparams_kernel(const float* __restrict__ gamma, const float* __restrict__ beta,
                                int C, float invN, int layer) {
    float* st = (layer == 1) ? g_stats1 : g_stats2;
    int c = threadIdx.x;
    if (c < C) {
        float mean = st[c] * invN;
        float var  = st[C + c] * invN - mean * mean;
        float s = gamma[c] * rsqrtf(var + EPS);
        st[2 * C + c] = s;
        st[3 * C + c] = beta[c] - mean * s;
    }
}

// ---------------- apply final BN2 in place on d_out ----------------
__global__ void bn2_apply_kernel(float* __restrict__ out, int total4) {
    int i = blockIdx.x * blockDim.x + threadIdx.x;
    if (i < total4) {
        float4 v = ((float4*)out)[i];
        int c = (i & 15) * 4;  // 64 cols = 16 float4s per row
        v.x = fmaf(v.x, g_stats2[2 * OUTC + c + 0], g_stats2[3 * OUTC + c + 0]);
        v.y = fmaf(v.y, g_stats2[2 * OUTC + c + 1], g_stats2[3 * OUTC + c + 1]);
        v.z = fmaf(v.z, g_stats2[2 * OUTC + c + 2], g_stats2[3 * OUTC + c + 2]);
        v.w = fmaf(v.w, g_stats2[2 * OUTC + c + 3], g_stats2[3 * OUTC + c + 3]);
        ((float4*)out)[i] = v;
    }
}

extern "C" void kernel_launch(void* const* d_in, const int* in_sizes, int n_in,
                              void* d_out, int out_size) {
    const float* x      = (const float*)d_in[0];
    const float* W1     = (const float*)d_in[1];
    const float* b1     = (const float*)d_in[2];
    const float* gamma1 = (const float*)d_in[3];
    const float* beta1  = (const float*)d_in[4];
    const float* W2     = (const float*)d_in[5];
    const float* b2     = (const float*)d_in[6];
    const float* gamma2 = (const float*)d_in[7];
    const float* beta2  = (const float*)d_in[8];
    const int*   ei     = (const int*)d_in[9];
    float*       out    = (float*)d_out;

    int N = in_sizes[0] / INC;     // 100000
    int E = in_sizes[9] / 2;       // 1600000
    const int* src = ei;
    const int* dst = ei + E;
    float invN = 1.0f / (float)N;

    // 1) CSR build + degrees
    zero_kernel<<<(N + 255) / 256, 256>>>(N);
    count_kernel<<<(E + 255) / 256, 256>>>(dst, E);
    scan_kernel<<<1, 1024>>>(N);
    fill_kernel<<<(E + 255) / 256, 256>>>(src, dst, E);

    // 2) g_h1 = (x @ W1) * dinv[row]
    gemm_kernel<64, 128, 4, 8, false><<<(N + 63) / 64, 256>>>(x, W1, N);

    // 3) aggregate layer 1 (+bias, +BN1 stats)
    agg128_kernel<<<1024, 256>>>(b1, N);
    bnparams_kernel<<<1, 128>>>(gamma1, beta1, HID, invN, 1);

    // 4) g_h2 = (relu(bn1(a1)) @ W2) * dinv[row]   (BN1+ReLU folded into A load)
    gemm_kernel<128, 64, 8, 4, true><<<(N + 127) / 128, 256>>>(nullptr, W2, N);

    // 5) aggregate layer 2 straight into d_out (+bias, +BN2 stats)
    agg64_kernel<<<1024, 256>>>(b2, out, N);
    bnparams_kernel<<<1, 64>>>(gamma2, beta2, OUTC, invN, 2);

    // 6) apply BN2 affine in place
    int total4 = N * OUTC / 4;
    bn2_apply_kernel<<<(total4 + 255) / 256, 256>>>(out, total4);
}

// round 5
// speedup vs baseline: 1.5963x; 1.5963x over previous
#include <cuda_runtime.h>
#include <cuda_bf16.h>
#include <cuda_fp16.h>
#include <cstdint>

#define NMAX 100000
#define EMAX 1600000
#define INC  128
#define HID  128
#define OUTC 64
#define EPS  1e-5f

// ---------------- scratch (no allocations allowed) ----------------
__device__ int    g_cnt[NMAX];
__device__ int    g_rowptr[NMAX + 1];
__device__ int    g_fill[NMAX];
__device__ int    g_col[EMAX];
__device__ float  g_dinv[NMAX];
__device__ int    g_bsum[128];
__device__ int    g_boff[128];
__device__ __half g_h1h[(size_t)NMAX * HID];   // (x@W1)*dinv, fp16
__device__ float  g_a1[(size_t)NMAX * HID];    // aggregated layer-1 (pre-BN), fp32
__device__ __half g_h2h[(size_t)NMAX * OUTC];  // (relu(bn1)@W2)*dinv, fp16
__device__ float  g_stats1[4 * HID];           // sum | sq | s | t
__device__ float  g_stats2[4 * OUTC];

// ---------------- helpers ----------------
__device__ __forceinline__ uint32_t smem_u32(const void* p) {
    uint32_t a;
    asm("{ .reg .u64 t; cvta.to.shared.u64 t, %1; cvt.u32.u64 %0, t; }" : "=r"(a) : "l"(p));
    return a;
}
__device__ __forceinline__ void ldmatrix_x4(uint32_t* r, uint32_t addr) {
    asm volatile("ldmatrix.sync.aligned.m8n8.x4.shared.b16 {%0,%1,%2,%3}, [%4];"
                 : "=r"(r[0]), "=r"(r[1]), "=r"(r[2]), "=r"(r[3]) : "r"(addr));
}
__device__ __forceinline__ void mma_bf16(float* c, const uint32_t* a, uint32_t b0, uint32_t b1) {
    asm volatile(
        "mma.sync.aligned.m16n8k16.row.col.f32.bf16.bf16.f32 "
        "{%0,%1,%2,%3}, {%4,%5,%6,%7}, {%8,%9}, {%0,%1,%2,%3};"
        : "+f"(c[0]), "+f"(c[1]), "+f"(c[2]), "+f"(c[3])
        : "r"(a[0]), "r"(a[1]), "r"(a[2]), "r"(a[3]), "r"(b0), "r"(b1));
}

// ---------------- init ----------------
__global__ void zero_kernel(int n) {
    int i = blockIdx.x * blockDim.x + threadIdx.x;
    if (i < n)        g_cnt[i] = 0;
    if (i < 4 * HID)  g_stats1[i] = 0.f;
    if (i < 4 * OUTC) g_stats2[i] = 0.f;
}

// ---------------- degree count ----------------
__global__ void count_kernel(const int* __restrict__ dst, int E) {
    int i = blockIdx.x * blockDim.x + threadIdx.x;
    if (i < E) atomicAdd(&g_cnt[dst[i]], 1);
}

// ---------------- 3-pass parallel scan ----------------
__global__ void scan1_kernel(int n) {
    __shared__ int ws[32];
    int tid = threadIdx.x, lane = tid & 31, w = tid >> 5;
    int i = blockIdx.x * 1024 + tid;
    int v = (i < n) ? g_cnt[i] : 0;
    int x = v;
    #pragma unroll
    for (int off = 1; off < 32; off <<= 1) {
        int y = __shfl_up_sync(0xffffffffu, x, off);
        if (lane >= off) x += y;
    }
    if (lane == 31) ws[w] = x;
    __syncthreads();
    if (w == 0) {
        int y = ws[lane];
        #pragma unroll
        for (int off = 1; off < 32; off <<= 1) {
            int z = __shfl_up_sync(0xffffffffu, y, off);
            if (lane >= off) y += z;
        }
        ws[lane] = y;
    }
    __syncthreads();
    int incl = x + (w ? ws[w - 1] : 0);
    if (i < n) g_fill[i] = incl - v;
    if (tid == 1023) g_bsum[blockIdx.x] = incl;
}
__global__ void scan2_kernel(int nb) {
    __shared__ int ws[4];
    int tid = threadIdx.x, lane = tid & 31, w = tid >> 5;
    int v = (tid < nb) ? g_bsum[tid] : 0;
    int x = v;
    #pragma unroll
    for (int off = 1; off < 32; off <<= 1) {
        int y = __shfl_up_sync(0xffffffffu, x, off);
        if (lane >= off) x += y;
    }
    if (lane == 31) ws[w] = x;
    __syncthreads();
    int add = 0;
    for (int j = 0; j < w; j++) add += ws[j];
    g_boff[tid] = x - v + add;
}
__global__ void scan3_kernel(int n) {
    int i = blockIdx.x * 1024 + threadIdx.x;
    if (i < n) {
        int off = g_boff[blockIdx.x];
        int c = g_cnt[i];
        int ex = g_fill[i] + off;
        g_fill[i] = ex;
        g_rowptr[i + 1] = ex + c;
        g_dinv[i] = rsqrtf((float)(c + 1));
        if (i == 0) g_rowptr[0] = 0;
    }
}

// ---------------- CSR fill ----------------
__global__ void fill_kernel(const int* __restrict__ src, const int* __restrict__ dst, int E) {
    int i = blockIdx.x * blockDim.x + threadIdx.x;
    if (i < E) {
        int d = dst[i];
        int pos = atomicAdd(&g_fill[d], 1);
        g_col[pos] = src[i];
    }
}

// ---------------- HMMA bf16 GEMM: C(half)[m,:] = (op(A)[m,:] @ W) * dinv[m] ----------------
// A and W split into bf16 hi/lo; D = Ah*Wh + Al*Wh + Ah*Wl accumulated in fp32.
// PRE_BN: A element -> relu(a * s[k] + t[k]) before split (BN1+ReLU folded into load).
// smem strides: 136 bf16 (272B) rows for both A and Wt (conflict-free ldmatrix / LDS).
#define ASTR 136
template <int TN, bool PRE_BN>
__global__ __launch_bounds__(256)
void mmagemm_kernel(const float* __restrict__ Aext, const float* __restrict__ W, int M) {
    extern __shared__ char smem[];
    const uint32_t SM_ST = 0;                       // s[128], t[128] floats
    const uint32_t A_HI  = 1024;
    const uint32_t A_LO  = A_HI + 128 * ASTR * 2;   // 34816 each
    const uint32_t B_HI  = A_LO + 128 * ASTR * 2;
    const uint32_t B_LO  = B_HI + TN * ASTR * 2;

    uint32_t sb = smem_u32(smem);
    int tid = threadIdx.x, wid = tid >> 5, lane = tid & 31;
    int m0 = blockIdx.x * 128;

    if (PRE_BN && tid < 256) {
        // s then t contiguously: [0..127]=s, [128..255]=t
        float v = (tid < 128) ? g_stats1[2 * HID + tid] : g_stats1[3 * HID + (tid - 128)];
        *(float*)(smem + SM_ST + tid * 4) = v;
    }

    const float* Asrc = PRE_BN ? g_a1 : Aext;
    __half* Cout = PRE_BN ? g_h2h : g_h1h;

    // --- A tile: 128 rows x 128 cols fp32 -> bf16 hi/lo ---
    const float* s = (const float*)(smem + SM_ST);
    const float* t = s + 128;
    if (PRE_BN) __syncthreads();
    #pragma unroll
    for (int it = 0; it < 16; ++it) {
        int idx = tid + it * 256;
        int row = idx >> 5;
        int col = (idx & 31) << 2;
        float4 v = make_float4(0.f, 0.f, 0.f, 0.f);
        if (m0 + row < M) v = *(const float4*)&Asrc[(size_t)(m0 + row) * 128 + col];
        if (PRE_BN) {
            v.x = fmaxf(fmaf(v.x, s[col + 0], t[col + 0]), 0.f);
            v.y = fmaxf(fmaf(v.y, s[col + 1], t[col + 1]), 0.f);
            v.z = fmaxf(fmaf(v.z, s[col + 2], t[col + 2]), 0.f);
            v.w = fmaxf(fmaf(v.w, s[col + 3], t[col + 3]), 0.f);
        }
        __nv_bfloat162 h01 = __floats2bfloat162_rn(v.x, v.y);
        __nv_bfloat162 h23 = __floats2bfloat162_rn(v.z, v.w);
        __nv_bfloat162 l01 = __floats2bfloat162_rn(v.x - __bfloat162float(h01.x),
                                                   v.y - __bfloat162float(h01.y));
        __nv_bfloat162 l23 = __floats2bfloat162_rn(v.z - __bfloat162float(h23.x),
                                                   v.w - __bfloat162float(h23.y));
        uint32_t off = (uint32_t)row * (ASTR * 2) + (uint32_t)col * 2;
        *(__nv_bfloat162*)(smem + A_HI + off)     = h01;
        *(__nv_bfloat162*)(smem + A_HI + off + 4) = h23;
        *(__nv_bfloat162*)(smem + A_LO + off)     = l01;
        *(__nv_bfloat162*)(smem + A_LO + off + 4) = l23;
    }
    // --- B: W [128, TN] row-major -> Wt[n][k] bf16 hi/lo ---
    for (int idx = tid; idx < 128 * TN; idx += 256) {
        int k = idx / TN, n = idx % TN;
        float w = W[idx];
        __nv_bfloat16 hi = __float2bfloat16_rn(w);
        __nv_bfloat16 lo = __float2bfloat16_rn(w - __bfloat162float(hi));
        uint32_t off = (uint32_t)n * (ASTR * 2) + (uint32_t)k * 2;
        *(__nv_bfloat16*)(smem + B_HI + off) = hi;
        *(__nv_bfloat16*)(smem + B_LO + off) = lo;
    }
    __syncthreads();

    // --- warp tiling: 8 warps; wm = wid&3 (32 rows), wn = wid>>2 (TN/2 cols) ---
    constexpr int WN   = TN / 2;   // 64 or 32
    constexpr int NSUB = WN / 8;   // 8 or 4
    int m_base = (wid & 3) * 32;
    int n_base = (wid >> 2) * WN;
    int g = lane >> 2, tt = lane & 3;

    float acc[2][NSUB][4];
    #pragma unroll
    for (int mi = 0; mi < 2; mi++)
        #pragma unroll
        for (int ni = 0; ni < NSUB; ni++)
            #pragma unroll
            for (int j = 0; j < 4; j++) acc[mi][ni][j] = 0.f;

    uint32_t a_row = (uint32_t)(m_base + (lane & 15));
    uint32_t a_cb  = (uint32_t)((lane >> 4) * 8);

    #pragma unroll
    for (int term = 0; term < 3; ++term) {
        uint32_t Abase = sb + ((term == 1) ? A_LO : A_HI);
        uint32_t Bbase = ((term == 2) ? B_LO : B_HI);
        #pragma unroll
        for (int ks = 0; ks < 8; ++ks) {
            int k0 = ks * 16;
            uint32_t af[2][4];
            #pragma unroll
            for (int mi = 0; mi < 2; mi++) {
                uint32_t addr = Abase + (a_row + mi * 16) * (ASTR * 2) + (a_cb + k0) * 2;
                ldmatrix_x4(af[mi], addr);
            }
            const char* brow = smem + Bbase + (uint32_t)(n_base + g) * (ASTR * 2) + (uint32_t)(k0 + 2 * tt) * 2;
            #pragma unroll
            for (int ni = 0; ni < NSUB; ni++) {
                uint32_t b0 = *(const uint32_t*)(brow + ni * 8 * (ASTR * 2));
                uint32_t b1 = *(const uint32_t*)(brow + ni * 8 * (ASTR * 2) + 16);
                mma_bf16(acc[0][ni], af[0], b0, b1);
                mma_bf16(acc[1][ni], af[1], b0, b1);
            }
        }
    }

    // --- epilogue: scale by dinv, fp16 out ---
    #pragma unroll
    for (int mi = 0; mi < 2; mi++) {
        int r0 = m0 + m_base + mi * 16 + g;
        int r1 = r0 + 8;
        float d0 = (r0 < M) ? g_dinv[r0] : 0.f;
        float d1 = (r1 < M) ? g_dinv[r1] : 0.f;
        #pragma unroll
        for (int ni = 0; ni < NSUB; ni++) {
            int col = n_base + ni * 8 + 2 * tt;
            if (r0 < M)
                *(__half2*)&Cout[(size_t)r0 * TN + col] =
                    __floats2half2_rn(acc[mi][ni][0] * d0, acc[mi][ni][1] * d0);
            if (r1 < M)
                *(__half2*)&Cout[(size_t)r1 * TN + col] =
                    __floats2half2_rn(acc[mi][ni][2] * d1, acc[mi][ni][3] * d1);
        }
    }
}

// ---------------- aggregation helpers ----------------
__device__ __forceinline__ float4 h4_to_f4(uint2 u) {
    float2 a = __half22float2(*(__half2*)&u.x);
    float2 b = __half22float2(*(__half2*)&u.y);
    return make_float4(a.x, a.y, b.x, b.y);
}

// ---------------- aggregation, 128 cols fp16 in, fp32 out ----------------
__global__ __launch_bounds__(256)
void agg128_kernel(const float* __restrict__ b, int n) {
    int gwarp  = (blockIdx.x * blockDim.x + threadIdx.x) >> 5;
    int lane   = threadIdx.x & 31;
    int nwarps = (gridDim.x * blockDim.x) >> 5;
    const uint2* base = (const uint2*)g_h1h;
    float4 bb = ((const float4*)b)[lane];
    float4 sum = make_float4(0, 0, 0, 0), sq = make_float4(0, 0, 0, 0);

    for (int node = gwarp; node < n; node += nwarps) {
        int e0 = g_rowptr[node], e1 = g_rowptr[node + 1];
        float4 acc = h4_to_f4(base[(size_t)node * 32 + lane]);  // self-loop
        int e = e0;
        for (; e + 4 <= e1; e += 4) {
            int i0 = g_col[e], i1 = g_col[e + 1], i2 = g_col[e + 2], i3 = g_col[e + 3];
            float4 v0 = h4_to_f4(base[(size_t)i0 * 32 + lane]);
            float4 v1 = h4_to_f4(base[(size_t)i1 * 32 + lane]);
            float4 v2 = h4_to_f4(base[(size_t)i2 * 32 + lane]);
            float4 v3 = h4_to_f4(base[(size_t)i3 * 32 + lane]);
            acc.x += (v0.x + v1.x) + (v2.x + v3.x);
            acc.y += (v0.y + v1.y) + (v2.y + v3.y);
            acc.z += (v0.z + v1.z) + (v2.z + v3.z);
            acc.w += (v0.w + v1.w) + (v2.w + v3.w);
        }
        for (; e < e1; e++) {
            float4 v = h4_to_f4(base[(size_t)g_col[e] * 32 + lane]);
            acc.x += v.x; acc.y += v.y; acc.z += v.z; acc.w += v.w;
        }
        float d = g_dinv[node];
        float4 o;
        o.x = fmaf(acc.x, d, bb.x); o.y = fmaf(acc.y, d, bb.y);
        o.z = fmaf(acc.z, d, bb.z); o.w = fmaf(acc.w, d, bb.w);
        ((float4*)g_a1)[(size_t)node * 32 + lane] = o;
        sum.x += o.x; sum.y += o.y; sum.z += o.z; sum.w += o.w;
        sq.x += o.x * o.x; sq.y += o.y * o.y; sq.z += o.z * o.z; sq.w += o.w * o.w;
    }
    __shared__ float ssum[HID], ssq[HID];
    int t = threadIdx.x;
    if (t < HID) { ssum[t] = 0.f; ssq[t] = 0.f; }
    __syncthreads();
    int c0 = lane * 4;
    atomicAdd(&ssum[c0 + 0], sum.x); atomicAdd(&ssum[c0 + 1], sum.y);
    atomicAdd(&ssum[c0 + 2], sum.z); atomicAdd(&ssum[c0 + 3], sum.w);
    atomicAdd(&ssq[c0 + 0], sq.x);  atomicAdd(&ssq[c0 + 1], sq.y);
    atomicAdd(&ssq[c0 + 2], sq.z);  atomicAdd(&ssq[c0 + 3], sq.w);
    __syncthreads();
    if (t < HID) {
        atomicAdd(&g_stats1[t], ssum[t]);
        atomicAdd(&g_stats1[HID + t], ssq[t]);
    }
}

// ---------------- aggregation, 64 cols fp16 in, fp32 out ----------------
__global__ __launch_bounds__(256)
void agg64_kernel(const float* __restrict__ b, float* __restrict__ out, int n) {
    int gwarp  = (blockIdx.x * blockDim.x + threadIdx.x) >> 5;
    int lane   = threadIdx.x & 31;
    int nwarps = (gridDim.x * blockDim.x) >> 5;
    const __half2* base = (const __half2*)g_h2h;
    float2 bb = ((const float2*)b)[lane];
    float2 sum = make_float2(0, 0), sq = make_float2(0, 0);

    for (int node = gwarp; node < n; node += nwarps) {
        int e0 = g_rowptr[node], e1 = g_rowptr[node + 1];
        float2 acc = __half22float2(base[(size_t)node * 32 + lane]);
        int e = e0;
        for (; e + 4 <= e1; e += 4) {
            int i0 = g_col[e], i1 = g_col[e + 1], i2 = g_col[e + 2], i3 = g_col[e + 3];
            float2 v0 = __half22float2(base[(size_t)i0 * 32 + lane]);
            float2 v1 = __half22float2(base[(size_t)i1 * 32 + lane]);
            float2 v2 = __half22float2(base[(size_t)i2 * 32 + lane]);
            float2 v3 = __half22float2(base[(size_t)i3 * 32 + lane]);
            acc.x += (v0.x + v1.x) + (v2.x + v3.x);
            acc.y += (v0.y + v1.y) + (v2.y + v3.y);
        }
        for (; e < e1; e++) {
            float2 v = __half22float2(base[(size_t)g_col[e] * 32 + lane]);
            acc.x += v.x; acc.y += v.y;
        }
        float d = g_dinv[node];
        float2 o;
        o.x = fmaf(acc.x, d, bb.x); o.y = fmaf(acc.y, d, bb.y);
        ((float2*)out)[(size_t)node * 32 + lane] = o;
        sum.x += o.x; sum.y += o.y;
        sq.x += o.x * o.x; sq.y += o.y * o.y;
    }
    __shared__ float ssum[OUTC], ssq[OUTC];
    int t = threadIdx.x;
    if (t < OUTC) { ssum[t] = 0.f; ssq[t] = 0.f; }
    __syncthreads();
    int c0 = lane * 2;
    atomicAdd(&ssum[c0 + 0], sum.x); atomicAdd(&ssum[c0 + 1], sum.y);
    atomicAdd(&ssq[c0 + 0], sq.x);  atomicAdd(&ssq[c0 + 1], sq.y);
    __syncthreads();
    if (t < OUTC) {
        atomicAdd(&g_stats2[t], ssum[t]);
        atomicAdd(&g_stats2[OUTC + t], ssq[t]);
    }
}

// ---------------- BN params ----------------
__global__ void bnparams_kernel(const float* __restrict__ gamma, const float* __restrict__ beta,
                                int C, float invN, int layer) {
    float* st = (layer == 1) ? g_stats1 : g_stats2;
    int c = threadIdx.x;
    if (c < C) {
        float mean = st[c] * invN;
        float var  = st[C + c] * invN - mean * mean;
        float s = gamma[c] * rsqrtf(var + EPS);
        st[2 * C + c] = s;
        st[3 * C + c] = beta[c] - mean * s;
    }
}

// ---------------- apply final BN2 in place on d_out ----------------
__global__ void bn2_apply_kernel(float* __restrict__ out, int total4) {
    int i = blockIdx.x * blockDim.x + threadIdx.x;
    if (i < total4) {
        float4 v = ((float4*)out)[i];
        int c = (i & 15) * 4;
        v.x = fmaf(v.x, g_stats2[2 * OUTC + c + 0], g_stats2[3 * OUTC + c + 0]);
        v.y = fmaf(v.y, g_stats2[2 * OUTC + c + 1], g_stats2[3 * OUTC + c + 1]);
        v.z = fmaf(v.z, g_stats2[2 * OUTC + c + 2], g_stats2[3 * OUTC + c + 2]);
        v.w = fmaf(v.w, g_stats2[2 * OUTC + c + 3], g_stats2[3 * OUTC + c + 3]);
        ((float4*)out)[i] = v;
    }
}

extern "C" void kernel_launch(void* const* d_in, const int* in_sizes, int n_in,
                              void* d_out, int out_size) {
    const float* x      = (const float*)d_in[0];
    const float* W1     = (const float*)d_in[1];
    const float* b1     = (const float*)d_in[2];
    const float* gamma1 = (const float*)d_in[3];
    const float* beta1  = (const float*)d_in[4];
    const float* W2     = (const float*)d_in[5];
    const float* b2     = (const float*)d_in[6];
    const float* gamma2 = (const float*)d_in[7];
    const float* beta2  = (const float*)d_in[8];
    const int*   ei     = (const int*)d_in[9];
    float*       out    = (float*)d_out;

    int N = in_sizes[0] / INC;     // 100000
    int E = in_sizes[9] / 2;       // 1600000
    const int* src = ei;
    const int* dst = ei + E;
    float invN = 1.0f / (float)N;

    // dynamic smem: 1024 (BN s/t) + A hi/lo (2*34816) + B hi/lo (2*TN*272)
    const int SMEM1 = 1024 + 2 * 128 * ASTR * 2 + 2 * 128 * ASTR * 2;  // 140288
    const int SMEM2 = 1024 + 2 * 128 * ASTR * 2 + 2 * 64 * ASTR * 2;   // 105472
    static bool attr_done = false;
    if (!attr_done) {
        cudaFuncSetAttribute(mmagemm_kernel<128, false>,
                             cudaFuncAttributeMaxDynamicSharedMemorySize, SMEM1);
        cudaFuncSetAttribute(mmagemm_kernel<64, true>,
                             cudaFuncAttributeMaxDynamicSharedMemorySize, SMEM2);
        attr_done = true;
    }

    int nb = (N + 1023) / 1024;

    // 1) CSR build + degrees
    zero_kernel<<<(N + 255) / 256, 256>>>(N);
    count_kernel<<<(E + 255) / 256, 256>>>(dst, E);
    scan1_kernel<<<nb, 1024>>>(N);
    scan2_kernel<<<1, 128>>>(nb);
    scan3_kernel<<<nb, 1024>>>(N);
    fill_kernel<<<(E + 255) / 256, 256>>>(src, dst, E);

    int gblk = (N + 127) / 128;
    // 2) h1 = (x @ W1) * dinv  -> fp16
    mmagemm_kernel<128, false><<<gblk, 256, SMEM1>>>(x, W1, N);
    // 3) aggregate layer 1 (+bias, +BN1 stats)
    agg128_kernel<<<1024, 256>>>(b1, N);
    bnparams_kernel<<<1, 128>>>(gamma1, beta1, HID, invN, 1);
    // 4) h2 = (relu(bn1(a1)) @ W2) * dinv -> fp16
    mmagemm_kernel<64, true><<<gblk, 256, SMEM2>>>(nullptr, W2, N);
    // 5) aggregate layer 2 into d_out (+bias, +BN2 stats)
    agg64_kernel<<<1024, 256>>>(b2, out, N);
    bnparams_kernel<<<1, 64>>>(gamma2, beta2, OUTC, invN, 2);
    // 6) apply BN2 affine in place
    int total4 = N * OUTC / 4;
    bn2_apply_kernel<<<(total4 + 255) / 256, 256>>>(out, total4);
}